// round 13
// baseline (speedup 1.0000x reference)
#include <cuda_runtime.h>
#include <cuda_fp16.h>
#include <cstdint>

// Problem constants
#define BB 32
#define LL 512
#define DD 384
#define KK 3
#define KTOT (DD * KK)        // 1152 GEMM-K
#define NROWS (BB * LL)       // 16384 GEMM-M

// Conv MMA tiling
#define MT 128                // M rows per CTA (L-tile)
#define NT 384                // full c_out per CTA
#define KC 64                 // K chunk
#define NCHUNK (KTOT / KC)    // 18
#define CTT 512               // 16 warps: 4 m x 4 n

// smem per stage:
//   A tiles (row-major, 128 rows x 144B): 18432B each (h,l)
//   B tile  (k-major, 64 rows x 784B padded rows, 384 halves used): 50176B
#define A_TILE_B 18432
#define B_TILE_B 50176
#define SM_AH 0
#define SM_AL A_TILE_B
#define SM_B  (2 * A_TILE_B)
#define STAGE_B (2 * A_TILE_B + B_TILE_B)   // 87040
#define RED1_OFF (2 * STAGE_B)               // float2[128][4] = 4096B
#define RED2_OFF (RED1_OFF + 4096)           // float[128][4]  = 2048B
#define SM_TOT (RED2_OFF + 2048)             // 180224

// epilogue modes
#define EP_SPLIT 0
#define EP_LN_SPLIT 1
#define EP_LN_DUR 2

// ---------------- device scratch (allocation-free) -------------------------
__device__ __align__(16) __half g_ah[NROWS * DD];
__device__ __align__(16) __half g_al[NROWS * DD];
__device__ __align__(16) __half g_bh[NROWS * DD];
__device__ __align__(16) __half g_bl[NROWS * DD];
__device__ __align__(16) __half g_w[4][KTOT * DD];   // [kappa][co], fp16
__device__ int g_cum[BB * LL];
__device__ int g_total[BB];

// ---------------- helpers --------------------------------------------------
__device__ __forceinline__ void hsplit(float v, __half& h, __half& l) {
    h = __float2half_rn(v);
    l = __float2half_rn(v - __half2float(h));
}
__device__ __forceinline__ uint32_t smem_u32(const void* p) {
    uint32_t a;
    asm("{ .reg .u64 t; cvta.to.shared.u64 t, %1; cvt.u32.u64 %0, t; }"
        : "=r"(a) : "l"(p));
    return a;
}

#define CP16(dst, src, sz)                                                     \
    asm volatile("cp.async.cg.shared.global [%0], [%1], 16, %2;"               \
                 :: "r"(dst), "l"(src), "r"(sz) : "memory")
#define CP_COMMIT()  asm volatile("cp.async.commit_group;" ::: "memory")
#define CP_WAIT(n)   asm volatile("cp.async.wait_group %0;" :: "n"(n) : "memory")

#define MMA_F16(c, a0, a1, a2, a3, b0, b1)                                     \
    asm volatile(                                                              \
        "mma.sync.aligned.m16n8k16.row.col.f32.f16.f16.f32 "                   \
        "{%0,%1,%2,%3},{%4,%5,%6,%7},{%8,%9},{%0,%1,%2,%3};"                   \
        : "+f"((c)[0]), "+f"((c)[1]), "+f"((c)[2]), "+f"((c)[3])               \
        : "r"(a0), "r"(a1), "r"(a2), "r"(a3), "r"(b0), "r"(b1))

#define LDSM4(r0, r1, r2, r3, addr)                                            \
    asm volatile("ldmatrix.sync.aligned.m8n8.x4.shared.b16 {%0,%1,%2,%3}, [%4];" \
        : "=r"(r0), "=r"(r1), "=r"(r2), "=r"(r3) : "r"(addr))
#define LDSM4T(r0, r1, r2, r3, addr)                                           \
    asm volatile("ldmatrix.sync.aligned.m8n8.x4.trans.shared.b16 {%0,%1,%2,%3}, [%4];" \
        : "=r"(r0), "=r"(r1), "=r"(r2), "=r"(r3) : "r"(addr))

// ---------------------------------------------------------------------------
// Conv1D(K=3,SAME)+bias+ReLU as HMMA fp16 GEMM, 2-term A-split:
//   C = (Ah + Al) * B_fp16
// 2-stage cp.async pipeline, ldmatrix loads, 128x384 CTA tile (full row).
// Grid (4, 32) = 128 CTAs (single wave), 512 threads, warp tile 32x96.
// Warps on the same SMSP (wid%4) process k-steps in rotated order
// (phase = wid>>2) so load-bursts and MMA-bursts interleave across warps.
// Epilogue modes: split only / fused LN + split / fused LN + linear head.
// ---------------------------------------------------------------------------
template<int MODE>
__global__ __launch_bounds__(CTT, 1) void conv_mma_kernel(
    const __half* __restrict__ ah, const __half* __restrict__ al,
    const __half* __restrict__ w,
    const float* __restrict__ bias,
    const float* __restrict__ gamma, const float* __restrict__ beta,
    const float* __restrict__ lw, const float* __restrict__ lb,
    __half* __restrict__ oh, __half* __restrict__ ol,
    float* __restrict__ dur)
{
    extern __shared__ char smem[];
    const uint32_t sb = smem_u32(smem);
    const int tid  = threadIdx.x;
    const int wid  = tid >> 5;
    const int lane = tid & 31;
    const int g    = lane >> 2;         // 0..7
    const int tg   = lane & 3;          // 0..3
    const int b    = blockIdx.y;
    const int l0   = blockIdx.x * MT;
    const int mBase = (wid & 3) * 32;   // 4 m-warps
    const int nBase = (wid >> 2) * 96;  // 4 n-warps
    const int kphase = wid >> 2;        // per-SMSP k-step stagger

    // ldmatrix lane-address components
    const int aRowSel = lane & 15;
    const int aColSel = (lane >> 4) * 16;
    const int bKSel   = ((lane >> 3) & 1) * 8 + (lane & 7);
    const int bNSel   = (lane >> 4) * 8;

    float acc[2][12][4];
#pragma unroll
    for (int mf = 0; mf < 2; mf++)
#pragma unroll
        for (int nf = 0; nf < 12; nf++)
#pragma unroll
            for (int q = 0; q < 4; q++) acc[mf][nf][q] = 0.f;

    // ---- staging (cp.async) ----
    auto stage = [&](int c, int s) {
        const uint32_t base = sb + s * STAGE_B;
        const int kappa0 = c * KC;
        const int seg = kappa0 / DD;
        const int ci0 = kappa0 - seg * DD;
        // A tiles: 128 rows x 8 x 16B (h and l), shifted by seg-1, zfill halo
        for (int idx = tid; idx < MT * 8; idx += CTT) {
            const int r = idx >> 3, gg = idx & 7;
            const int l = l0 + r + seg - 1;
            const int ok = ((unsigned)l < LL) ? 16 : 0;
            const size_t go = ((size_t)(b * LL + ((unsigned)l < LL ? l : 0))) * DD
                              + ci0 + gg * 8;
            const uint32_t so = r * 144 + gg * 16;
            CP16(base + SM_AH + so, ah + go, ok);
            CP16(base + SM_AL + so, al + go, ok);
        }
        // B tile: 64 k-rows x 48 x 16B; gmem w is [kappa][co] fp16
        for (int idx = tid; idx < KC * 48; idx += CTT) {
            const int kr = idx / 48, gg = idx - kr * 48;
            const size_t go = (size_t)(kappa0 + kr) * DD + gg * 8;
            const uint32_t so = kr * 784 + gg * 16;
            CP16(base + SM_B + so, w + go, 16);
        }
        CP_COMMIT();
    };

    stage(0, 0);

    for (int c = 0; c < NCHUNK; c++) {
        const int s = c & 1;
        if (c + 1 < NCHUNK) {
            stage(c + 1, s ^ 1);
            CP_WAIT(1);
        } else {
            CP_WAIT(0);
        }
        __syncthreads();

        const uint32_t stA = sb + s * STAGE_B + SM_AH;
        const uint32_t stB = sb + s * STAGE_B + SM_B;

#pragma unroll
        for (int kk0 = 0; kk0 < 4; kk0++) {         // K=16 steps in chunk
            const int kk = (kk0 + kphase) & 3;      // staggered per SMSP
            // B fragments: 6 LDSM4T -> 12 nf
            uint32_t bf[12][2];
#pragma unroll
            for (int p = 0; p < 6; p++) {
                const uint32_t bad = stB + (kk * 16 + bKSel) * 784
                                   + (nBase + p * 16 + bNSel) * 2;
                LDSM4T(bf[p * 2][0], bf[p * 2][1],
                       bf[p * 2 + 1][0], bf[p * 2 + 1][1], bad);
            }
#pragma unroll
            for (int mf = 0; mf < 2; mf++) {
                const uint32_t aad = stA + (mBase + mf * 16 + aRowSel) * 144
                                   + kk * 32 + aColSel;
                uint32_t a0, a1, a2, a3, c0, c1, c2, c3;
                LDSM4(a0, a1, a2, a3, aad);
                LDSM4(c0, c1, c2, c3, aad + A_TILE_B);
                // term-separated: dependent MMAs 12 issues apart
#pragma unroll
                for (int nf = 0; nf < 12; nf++)
                    MMA_F16(acc[mf][nf], a0, a1, a2, a3, bf[nf][0], bf[nf][1]);
#pragma unroll
                for (int nf = 0; nf < 12; nf++)
                    MMA_F16(acc[mf][nf], c0, c1, c2, c3, bf[nf][0], bf[nf][1]);
            }
        }
        __syncthreads();   // compute done before buffer s is restaged
    }

    // ---- epilogue ----
    // bias + ReLU in place
#pragma unroll
    for (int nf = 0; nf < 12; nf++) {
        const int c0 = nBase + nf * 8 + tg * 2;
        const float bi0 = __ldg(bias + c0);
        const float bi1 = __ldg(bias + c0 + 1);
#pragma unroll
        for (int mf = 0; mf < 2; mf++) {
            acc[mf][nf][0] = fmaxf(acc[mf][nf][0] + bi0, 0.f);
            acc[mf][nf][1] = fmaxf(acc[mf][nf][1] + bi1, 0.f);
            acc[mf][nf][2] = fmaxf(acc[mf][nf][2] + bi0, 0.f);
            acc[mf][nf][3] = fmaxf(acc[mf][nf][3] + bi1, 0.f);
        }
    }

    float mu[2][2], rs[2][2];
    if (MODE >= EP_LN_SPLIT) {
        float2* red = reinterpret_cast<float2*>(smem + RED1_OFF);
        const int nw = wid >> 2;
#pragma unroll
        for (int mf = 0; mf < 2; mf++)
#pragma unroll
            for (int hi = 0; hi < 2; hi++) {
                float s = 0.f, s2 = 0.f;
#pragma unroll
                for (int nf = 0; nf < 12; nf++) {
                    float a = acc[mf][nf][hi * 2];
                    float bq = acc[mf][nf][hi * 2 + 1];
                    s  += a + bq;
                    s2 += a * a + bq * bq;
                }
                s  += __shfl_xor_sync(0xffffffffu, s, 1);
                s  += __shfl_xor_sync(0xffffffffu, s, 2);
                s2 += __shfl_xor_sync(0xffffffffu, s2, 1);
                s2 += __shfl_xor_sync(0xffffffffu, s2, 2);
                if (tg == 0)
                    red[(mBase + mf * 16 + g + hi * 8) * 4 + nw] =
                        make_float2(s, s2);
            }
        __syncthreads();
#pragma unroll
        for (int mf = 0; mf < 2; mf++)
#pragma unroll
            for (int hi = 0; hi < 2; hi++) {
                const int r = mBase + mf * 16 + g + hi * 8;
                float2 p0 = red[r * 4 + 0], p1 = red[r * 4 + 1];
                float2 p2 = red[r * 4 + 2], p3 = red[r * 4 + 3];
                float s  = p0.x + p1.x + p2.x + p3.x;
                float s2v = p0.y + p1.y + p2.y + p3.y;
                const float inv = 1.f / (float)DD;
                float m = s * inv;
                mu[mf][hi] = m;
                rs[mf][hi] = rsqrtf(s2v * inv - m * m + 1e-5f);
            }
    }

    float dsum[2][2] = {{0.f, 0.f}, {0.f, 0.f}};
#pragma unroll
    for (int nf = 0; nf < 12; nf++) {
        const int c0 = nBase + nf * 8 + tg * 2;
        float ga0 = 1.f, ga1 = 1.f, be0 = 0.f, be1 = 0.f, w0 = 0.f, w1 = 0.f;
        if (MODE >= EP_LN_SPLIT) {
            ga0 = __ldg(gamma + c0);  ga1 = __ldg(gamma + c0 + 1);
            be0 = __ldg(beta + c0);   be1 = __ldg(beta + c0 + 1);
        }
        if (MODE == EP_LN_DUR) {
            w0 = __ldg(lw + c0);      w1 = __ldg(lw + c0 + 1);
        }
#pragma unroll
        for (int mf = 0; mf < 2; mf++) {
            const int m0 = mBase + mf * 16 + g;
            float o[4];
#pragma unroll
            for (int hi = 0; hi < 2; hi++) {
                float v0 = acc[mf][nf][hi * 2];
                float v1 = acc[mf][nf][hi * 2 + 1];
                if (MODE >= EP_LN_SPLIT) {
                    v0 = (v0 - mu[mf][hi]) * rs[mf][hi] * ga0 + be0;
                    v1 = (v1 - mu[mf][hi]) * rs[mf][hi] * ga1 + be1;
                }
                o[hi * 2]     = v0;
                o[hi * 2 + 1] = v1;
                if (MODE == EP_LN_DUR)
                    dsum[mf][hi] += v0 * w0 + v1 * w1;
            }
            if (MODE != EP_LN_DUR) {
                const size_t grow0 = ((size_t)(b * LL + l0 + m0)) * DD + c0;
                const size_t grow1 = grow0 + 8 * DD;
                __half h0, q0, h1, q1, h2, q2, h3, q3;
                hsplit(o[0], h0, q0); hsplit(o[1], h1, q1);
                hsplit(o[2], h2, q2); hsplit(o[3], h3, q3);
                *reinterpret_cast<uint32_t*>(oh + grow0) =
                    (uint32_t)__half_as_ushort(h0) |
                    ((uint32_t)__half_as_ushort(h1) << 16);
                *reinterpret_cast<uint32_t*>(ol + grow0) =
                    (uint32_t)__half_as_ushort(q0) |
                    ((uint32_t)__half_as_ushort(q1) << 16);
                *reinterpret_cast<uint32_t*>(oh + grow1) =
                    (uint32_t)__half_as_ushort(h2) |
                    ((uint32_t)__half_as_ushort(h3) << 16);
                *reinterpret_cast<uint32_t*>(ol + grow1) =
                    (uint32_t)__half_as_ushort(q2) |
                    ((uint32_t)__half_as_ushort(q3) << 16);
            }
        }
    }

    if (MODE == EP_LN_DUR) {
        float* red2 = reinterpret_cast<float*>(smem + RED2_OFF);
        const int nw = wid >> 2;
#pragma unroll
        for (int mf = 0; mf < 2; mf++)
#pragma unroll
            for (int hi = 0; hi < 2; hi++) {
                float d = dsum[mf][hi];
                d += __shfl_xor_sync(0xffffffffu, d, 1);
                d += __shfl_xor_sync(0xffffffffu, d, 2);
                if (tg == 0)
                    red2[(mBase + mf * 16 + g + hi * 8) * 4 + nw] = d;
            }
        __syncthreads();
        if ((wid >> 2) == 0 && tg == 0) {
            const float lb0 = __ldg(lb);
#pragma unroll
            for (int mf = 0; mf < 2; mf++)
#pragma unroll
                for (int hi = 0; hi < 2; hi++) {
                    const int r = mBase + mf * 16 + g + hi * 8;
                    dur[(size_t)(b * LL + l0 + r)] =
                        red2[r * 4 + 0] + red2[r * 4 + 1] +
                        red2[r * 4 + 2] + red2[r * 4 + 3] + lb0;
                }
        }
    }
}

// ---------------------------------------------------------------------------
// Split fp32 -> fp16 hi/lo (for initial x)
// ---------------------------------------------------------------------------
__global__ void split_kernel(const float* __restrict__ x,
                             __half* __restrict__ oh,
                             __half* __restrict__ ol, int n)
{
    int i = blockIdx.x * blockDim.x + threadIdx.x;
    if (i >= n) return;
    __half h, l;
    hsplit(x[i], h, l);
    oh[i] = h;
    ol[i] = l;
}

// ---------------------------------------------------------------------------
// Weight prep for all 4 layers (blockIdx.z = layer):
// w[co][ci][k] fp32 -> w[kappa][co] fp16 (kappa = k*384+ci)
// ---------------------------------------------------------------------------
__global__ void wprepT_kernel(const float* __restrict__ w0,
                              const float* __restrict__ w1,
                              const float* __restrict__ w2,
                              const float* __restrict__ w3,
                              __half* __restrict__ wb)
{
    __shared__ float t[32][33];
    const int layer = blockIdx.z;
    const float* w = (layer == 0) ? w0 : (layer == 1) ? w1 : (layer == 2) ? w2 : w3;
    __half* wt = wb + (size_t)layer * KTOT * DD;

    const int ka0 = blockIdx.x * 32;
    const int co0 = blockIdx.y * 32;
    const int tx = threadIdx.x, ty = threadIdx.y;
    const int k   = ka0 / DD;
    const int ci0 = ka0 - k * DD;

#pragma unroll
    for (int i = 0; i < 32; i += 8) {
        const int co = co0 + ty + i;
        const int ci = ci0 + tx;
        t[ty + i][tx] = w[(size_t)co * KTOT + ci * KK + k];
    }
    __syncthreads();
#pragma unroll
    for (int i = 0; i < 32; i += 8) {
        const int ka = ka0 + ty + i;
        const int co = co0 + tx;
        wt[(size_t)ka * DD + co] = __float2half_rn(t[tx][ty + i]);
    }
}

// ---------------------------------------------------------------------------
// Serial inclusive prefix scan: one thread per batch.
// ---------------------------------------------------------------------------
__global__ void serial_scan_kernel(const int* __restrict__ dur,
                                   int* __restrict__ cum,
                                   int* __restrict__ total)
{
    int b = threadIdx.x;
    if (b >= BB) return;
    int acc = 0;
    const int* dr = dur + b * LL;
    int* cr = cum + b * LL;
    for (int l = 0; l < LL; l++) {
        acc += dr[l];
        cr[l] = acc;
    }
    total[b] = acc;
}

// ---------------------------------------------------------------------------
// Length regulator scatter + tail zero (proven correct).
// ---------------------------------------------------------------------------
__global__ __launch_bounds__(128) void scatter_kernel(
    const float* __restrict__ x, const int* __restrict__ cum,
    float* __restrict__ out, int T)
{
    int l = blockIdx.x;
    int b = blockIdx.y;
    int lane = threadIdx.x;

    int end   = cum[b * LL + l];
    int start = (l == 0) ? 0 : cum[b * LL + l - 1];
    if (start == end) return;

    const float* xr = x + ((size_t)(b * LL + l)) * DD;
    float r0 = xr[lane];
    float r1 = xr[lane + 128];
    float r2 = xr[lane + 256];

    for (int t = start; t < end; t++) {
        float* o = out + ((size_t)b * T + t) * DD;
        o[lane]       = r0;
        o[lane + 128] = r1;
        o[lane + 256] = r2;
    }
}

__global__ __launch_bounds__(128) void zero_tail_kernel(
    const int* __restrict__ total, float* __restrict__ out, int T)
{
    int t = blockIdx.x;
    int b = blockIdx.y;
    if (t < total[b]) return;
    int lane = threadIdx.x;
    float* o = out + ((size_t)b * T + t) * DD;
    o[lane]       = 0.f;
    o[lane + 128] = 0.f;
    o[lane + 256] = 0.f;
}

// ---------------------------------------------------------------------------
extern "C" void kernel_launch(void* const* d_in, const int* in_sizes, int n_in,
                              void* d_out, int out_size)
{
    const float* x     = (const float*)d_in[0];
    const int*   dur   = (const int*)  d_in[1];
    const float* c1a_w = (const float*)d_in[2];
    const float* c1a_b = (const float*)d_in[3];
    const float* c1b_w = (const float*)d_in[4];
    const float* c1b_b = (const float*)d_in[5];
    const float* ln1_g = (const float*)d_in[6];
    const float* ln1_b = (const float*)d_in[7];
    const float* c2a_w = (const float*)d_in[8];
    const float* c2a_b = (const float*)d_in[9];
    const float* c2b_w = (const float*)d_in[10];
    const float* c2b_b = (const float*)d_in[11];
    const float* ln2_g = (const float*)d_in[12];
    const float* ln2_b = (const float*)d_in[13];
    const float* lin_w = (const float*)d_in[14];
    const float* lin_b = (const float*)d_in[15];
    float* out = (float*)d_out;

    long T = ((long)out_size - (long)BB * LL) / ((long)BB * DD);

    __half *ah, *al, *bh, *bl, *w;
    int *cum, *total;
    cudaGetSymbolAddress((void**)&ah,    g_ah);
    cudaGetSymbolAddress((void**)&al,    g_al);
    cudaGetSymbolAddress((void**)&bh,    g_bh);
    cudaGetSymbolAddress((void**)&bl,    g_bl);
    cudaGetSymbolAddress((void**)&w,     g_w);
    cudaGetSymbolAddress((void**)&cum,   g_cum);
    cudaGetSymbolAddress((void**)&total, g_total);

    cudaFuncSetAttribute(conv_mma_kernel<EP_SPLIT>,
                         cudaFuncAttributeMaxDynamicSharedMemorySize, SM_TOT);
    cudaFuncSetAttribute(conv_mma_kernel<EP_LN_SPLIT>,
                         cudaFuncAttributeMaxDynamicSharedMemorySize, SM_TOT);
    cudaFuncSetAttribute(conv_mma_kernel<EP_LN_DUR>,
                         cudaFuncAttributeMaxDynamicSharedMemorySize, SM_TOT);

    const int WN = KTOT * DD;
    const int n  = NROWS * DD;

    // Prep: operand splits (weights transposed to [kappa][co] fp16)
    split_kernel<<<(n + 255) / 256, 256>>>(x, ah, al, n);
    dim3 wtg(KTOT / 32, DD / 32, 4);
    dim3 wtb(32, 8);
    wprepT_kernel<<<wtg, wtb>>>(c1a_w, c1b_w, c2a_w, c2b_w, w);

    dim3 cgrid(LL / MT, BB);   // (4, 32) = 128 CTAs, single wave
    float* dur_out = out + (size_t)BB * T * DD;

    // Duration predictor (fp16 2-term HMMA convs; LN / lin head fused)
    conv_mma_kernel<EP_SPLIT><<<cgrid, CTT, SM_TOT>>>(
        ah, al, w,          c1a_b, nullptr, nullptr, nullptr, nullptr,
        bh, bl, nullptr);
    conv_mma_kernel<EP_LN_SPLIT><<<cgrid, CTT, SM_TOT>>>(
        bh, bl, w + WN,     c1b_b, ln1_g, ln1_b, nullptr, nullptr,
        ah, al, nullptr);
    conv_mma_kernel<EP_SPLIT><<<cgrid, CTT, SM_TOT>>>(
        ah, al, w + 2 * WN, c2a_b, nullptr, nullptr, nullptr, nullptr,
        bh, bl, nullptr);
    conv_mma_kernel<EP_LN_DUR><<<cgrid, CTT, SM_TOT>>>(
        bh, bl, w + 3 * WN, c2b_b, ln2_g, ln2_b, lin_w, lin_b,
        nullptr, nullptr, dur_out);

    // Length regulator
    serial_scan_kernel<<<1, BB>>>(dur, cum, total);
    zero_tail_kernel<<<dim3((unsigned)T, BB), 128>>>(total, out, (int)T);
    scatter_kernel<<<dim3(LL, BB), 128>>>(x, cum, out, (int)T);
}

// round 14
// speedup vs baseline: 1.0009x; 1.0009x over previous
#include <cuda_runtime.h>
#include <cuda_fp16.h>
#include <cstdint>

// Problem constants
#define BB 32
#define LL 512
#define DD 384
#define KK 3
#define KTOT (DD * KK)        // 1152 GEMM-K
#define NROWS (BB * LL)       // 16384 GEMM-M

// Conv MMA tiling
#define MT 128                // M rows per CTA (L-tile)
#define NT 384                // full c_out per CTA
#define KC 64                 // K chunk
#define NCHUNK (KTOT / KC)    // 18
#define CTT 512               // 16 warps: 4 m x 4 n

// smem per stage:
//   A tiles (row-major, 128 rows x 144B): 18432B each (h,l)
//   B tile  (k-major, 64 rows x 784B padded rows, 384 halves used): 50176B
#define A_TILE_B 18432
#define B_TILE_B 50176
#define SM_AH 0
#define SM_AL A_TILE_B
#define SM_B  (2 * A_TILE_B)
#define STAGE_B (2 * A_TILE_B + B_TILE_B)   // 87040
#define RED1_OFF (2 * STAGE_B)               // float2[128][4] = 4096B
#define RED2_OFF (RED1_OFF + 4096)           // float[128][4]  = 2048B
#define SM_TOT (RED2_OFF + 2048)             // 180224

// epilogue modes
#define EP_SPLIT 0
#define EP_LN_SPLIT 1
#define EP_LN_DUR 2

// ---------------- device scratch (allocation-free) -------------------------
__device__ __align__(16) __half g_ah[NROWS * DD];
__device__ __align__(16) __half g_al[NROWS * DD];
__device__ __align__(16) __half g_bh[NROWS * DD];
__device__ __align__(16) __half g_bl[NROWS * DD];
__device__ __align__(16) __half g_w[4][KTOT * DD];   // [kappa][co], fp16
__device__ int g_cum[BB * LL];
__device__ int g_total[BB];

// ---------------- helpers --------------------------------------------------
__device__ __forceinline__ void hsplit(float v, __half& h, __half& l) {
    h = __float2half_rn(v);
    l = __float2half_rn(v - __half2float(h));
}
__device__ __forceinline__ uint32_t smem_u32(const void* p) {
    uint32_t a;
    asm("{ .reg .u64 t; cvta.to.shared.u64 t, %1; cvt.u32.u64 %0, t; }"
        : "=r"(a) : "l"(p));
    return a;
}

#define CP16(dst, src, sz)                                                     \
    asm volatile("cp.async.cg.shared.global [%0], [%1], 16, %2;"               \
                 :: "r"(dst), "l"(src), "r"(sz) : "memory")
#define CP_COMMIT()  asm volatile("cp.async.commit_group;" ::: "memory")
#define CP_WAIT(n)   asm volatile("cp.async.wait_group %0;" :: "n"(n) : "memory")

#define MMA_F16(c, a0, a1, a2, a3, b0, b1)                                     \
    asm volatile(                                                              \
        "mma.sync.aligned.m16n8k16.row.col.f32.f16.f16.f32 "                   \
        "{%0,%1,%2,%3},{%4,%5,%6,%7},{%8,%9},{%0,%1,%2,%3};"                   \
        : "+f"((c)[0]), "+f"((c)[1]), "+f"((c)[2]), "+f"((c)[3])               \
        : "r"(a0), "r"(a1), "r"(a2), "r"(a3), "r"(b0), "r"(b1))

#define LDSM4(r0, r1, r2, r3, addr)                                            \
    asm volatile("ldmatrix.sync.aligned.m8n8.x4.shared.b16 {%0,%1,%2,%3}, [%4];" \
        : "=r"(r0), "=r"(r1), "=r"(r2), "=r"(r3) : "r"(addr))
#define LDSM4T(r0, r1, r2, r3, addr)                                           \
    asm volatile("ldmatrix.sync.aligned.m8n8.x4.trans.shared.b16 {%0,%1,%2,%3}, [%4];" \
        : "=r"(r0), "=r"(r1), "=r"(r2), "=r"(r3) : "r"(addr))

// ---------------------------------------------------------------------------
// Conv1D(K=3,SAME)+bias+ReLU as HMMA fp16 GEMM, 2-term A-split:
//   C = (Ah + Al) * B_fp16
// 2-stage cp.async pipeline, ldmatrix loads, 128x384 CTA tile (full row).
// Grid (4, 32) = 128 CTAs (single wave), 512 threads, warp tile 32x96.
// Warps on the same SMSP (wid%4) process k-steps in rotated order
// (phase = wid>>2) so load-bursts and MMA-bursts interleave across warps.
// Epilogue modes: split only / fused LN + split / fused LN + linear head.
// ---------------------------------------------------------------------------
template<int MODE>
__global__ __launch_bounds__(CTT, 1) void conv_mma_kernel(
    const __half* __restrict__ ah, const __half* __restrict__ al,
    const __half* __restrict__ w,
    const float* __restrict__ bias,
    const float* __restrict__ gamma, const float* __restrict__ beta,
    const float* __restrict__ lw, const float* __restrict__ lb,
    __half* __restrict__ oh, __half* __restrict__ ol,
    float* __restrict__ dur)
{
    extern __shared__ char smem[];
    const uint32_t sb = smem_u32(smem);
    const int tid  = threadIdx.x;
    const int wid  = tid >> 5;
    const int lane = tid & 31;
    const int g    = lane >> 2;         // 0..7
    const int tg   = lane & 3;          // 0..3
    const int b    = blockIdx.y;
    const int l0   = blockIdx.x * MT;
    const int mBase = (wid & 3) * 32;   // 4 m-warps
    const int nBase = (wid >> 2) * 96;  // 4 n-warps
    const int kphase = wid >> 2;        // per-SMSP k-step stagger

    // ldmatrix lane-address components
    const int aRowSel = lane & 15;
    const int aColSel = (lane >> 4) * 16;
    const int bKSel   = ((lane >> 3) & 1) * 8 + (lane & 7);
    const int bNSel   = (lane >> 4) * 8;

    float acc[2][12][4];
#pragma unroll
    for (int mf = 0; mf < 2; mf++)
#pragma unroll
        for (int nf = 0; nf < 12; nf++)
#pragma unroll
            for (int q = 0; q < 4; q++) acc[mf][nf][q] = 0.f;

    // ---- staging (cp.async) ----
    auto stage = [&](int c, int s) {
        const uint32_t base = sb + s * STAGE_B;
        const int kappa0 = c * KC;
        const int seg = kappa0 / DD;
        const int ci0 = kappa0 - seg * DD;
        // A tiles: 128 rows x 8 x 16B (h and l), shifted by seg-1, zfill halo
        for (int idx = tid; idx < MT * 8; idx += CTT) {
            const int r = idx >> 3, gg = idx & 7;
            const int l = l0 + r + seg - 1;
            const int ok = ((unsigned)l < LL) ? 16 : 0;
            const size_t go = ((size_t)(b * LL + ((unsigned)l < LL ? l : 0))) * DD
                              + ci0 + gg * 8;
            const uint32_t so = r * 144 + gg * 16;
            CP16(base + SM_AH + so, ah + go, ok);
            CP16(base + SM_AL + so, al + go, ok);
        }
        // B tile: 64 k-rows x 48 x 16B; gmem w is [kappa][co] fp16
        for (int idx = tid; idx < KC * 48; idx += CTT) {
            const int kr = idx / 48, gg = idx - kr * 48;
            const size_t go = (size_t)(kappa0 + kr) * DD + gg * 8;
            const uint32_t so = kr * 784 + gg * 16;
            CP16(base + SM_B + so, w + go, 16);
        }
        CP_COMMIT();
    };

    stage(0, 0);

    for (int c = 0; c < NCHUNK; c++) {
        const int s = c & 1;
        if (c + 1 < NCHUNK) {
            stage(c + 1, s ^ 1);
            CP_WAIT(1);
        } else {
            CP_WAIT(0);
        }
        __syncthreads();

        const uint32_t stA = sb + s * STAGE_B + SM_AH;
        const uint32_t stB = sb + s * STAGE_B + SM_B;

#pragma unroll
        for (int kk0 = 0; kk0 < 4; kk0++) {         // K=16 steps in chunk
            const int kk = (kk0 + kphase) & 3;      // staggered per SMSP
            // B fragments: 6 LDSM4T -> 12 nf
            uint32_t bf[12][2];
#pragma unroll
            for (int p = 0; p < 6; p++) {
                const uint32_t bad = stB + (kk * 16 + bKSel) * 784
                                   + (nBase + p * 16 + bNSel) * 2;
                LDSM4T(bf[p * 2][0], bf[p * 2][1],
                       bf[p * 2 + 1][0], bf[p * 2 + 1][1], bad);
            }
#pragma unroll
            for (int mf = 0; mf < 2; mf++) {
                const uint32_t aad = stA + (mBase + mf * 16 + aRowSel) * 144
                                   + kk * 32 + aColSel;
                uint32_t a0, a1, a2, a3, c0, c1, c2, c3;
                LDSM4(a0, a1, a2, a3, aad);
                LDSM4(c0, c1, c2, c3, aad + A_TILE_B);
                // term-separated: dependent MMAs 12 issues apart
#pragma unroll
                for (int nf = 0; nf < 12; nf++)
                    MMA_F16(acc[mf][nf], a0, a1, a2, a3, bf[nf][0], bf[nf][1]);
#pragma unroll
                for (int nf = 0; nf < 12; nf++)
                    MMA_F16(acc[mf][nf], c0, c1, c2, c3, bf[nf][0], bf[nf][1]);
            }
        }
        __syncthreads();   // compute done before buffer s is restaged
    }

    // ---- epilogue ----
    // bias + ReLU in place
#pragma unroll
    for (int nf = 0; nf < 12; nf++) {
        const int c0 = nBase + nf * 8 + tg * 2;
        const float bi0 = __ldg(bias + c0);
        const float bi1 = __ldg(bias + c0 + 1);
#pragma unroll
        for (int mf = 0; mf < 2; mf++) {
            acc[mf][nf][0] = fmaxf(acc[mf][nf][0] + bi0, 0.f);
            acc[mf][nf][1] = fmaxf(acc[mf][nf][1] + bi1, 0.f);
            acc[mf][nf][2] = fmaxf(acc[mf][nf][2] + bi0, 0.f);
            acc[mf][nf][3] = fmaxf(acc[mf][nf][3] + bi1, 0.f);
        }
    }

    float mu[2][2], rs[2][2];
    if (MODE >= EP_LN_SPLIT) {
        float2* red = reinterpret_cast<float2*>(smem + RED1_OFF);
        const int nw = wid >> 2;
#pragma unroll
        for (int mf = 0; mf < 2; mf++)
#pragma unroll
            for (int hi = 0; hi < 2; hi++) {
                float s = 0.f, s2 = 0.f;
#pragma unroll
                for (int nf = 0; nf < 12; nf++) {
                    float a = acc[mf][nf][hi * 2];
                    float bq = acc[mf][nf][hi * 2 + 1];
                    s  += a + bq;
                    s2 += a * a + bq * bq;
                }
                s  += __shfl_xor_sync(0xffffffffu, s, 1);
                s  += __shfl_xor_sync(0xffffffffu, s, 2);
                s2 += __shfl_xor_sync(0xffffffffu, s2, 1);
                s2 += __shfl_xor_sync(0xffffffffu, s2, 2);
                if (tg == 0)
                    red[(mBase + mf * 16 + g + hi * 8) * 4 + nw] =
                        make_float2(s, s2);
            }
        __syncthreads();
#pragma unroll
        for (int mf = 0; mf < 2; mf++)
#pragma unroll
            for (int hi = 0; hi < 2; hi++) {
                const int r = mBase + mf * 16 + g + hi * 8;
                float2 p0 = red[r * 4 + 0], p1 = red[r * 4 + 1];
                float2 p2 = red[r * 4 + 2], p3 = red[r * 4 + 3];
                float s  = p0.x + p1.x + p2.x + p3.x;
                float s2v = p0.y + p1.y + p2.y + p3.y;
                const float inv = 1.f / (float)DD;
                float m = s * inv;
                mu[mf][hi] = m;
                rs[mf][hi] = rsqrtf(s2v * inv - m * m + 1e-5f);
            }
    }

    float dsum[2][2] = {{0.f, 0.f}, {0.f, 0.f}};
#pragma unroll
    for (int nf = 0; nf < 12; nf++) {
        const int c0 = nBase + nf * 8 + tg * 2;
        float ga0 = 1.f, ga1 = 1.f, be0 = 0.f, be1 = 0.f, w0 = 0.f, w1 = 0.f;
        if (MODE >= EP_LN_SPLIT) {
            ga0 = __ldg(gamma + c0);  ga1 = __ldg(gamma + c0 + 1);
            be0 = __ldg(beta + c0);   be1 = __ldg(beta + c0 + 1);
        }
        if (MODE == EP_LN_DUR) {
            w0 = __ldg(lw + c0);      w1 = __ldg(lw + c0 + 1);
        }
#pragma unroll
        for (int mf = 0; mf < 2; mf++) {
            const int m0 = mBase + mf * 16 + g;
            float o[4];
#pragma unroll
            for (int hi = 0; hi < 2; hi++) {
                float v0 = acc[mf][nf][hi * 2];
                float v1 = acc[mf][nf][hi * 2 + 1];
                if (MODE >= EP_LN_SPLIT) {
                    v0 = (v0 - mu[mf][hi]) * rs[mf][hi] * ga0 + be0;
                    v1 = (v1 - mu[mf][hi]) * rs[mf][hi] * ga1 + be1;
                }
                o[hi * 2]     = v0;
                o[hi * 2 + 1] = v1;
                if (MODE == EP_LN_DUR)
                    dsum[mf][hi] += v0 * w0 + v1 * w1;
            }
            if (MODE != EP_LN_DUR) {
                const size_t grow0 = ((size_t)(b * LL + l0 + m0)) * DD + c0;
                const size_t grow1 = grow0 + 8 * DD;
                __half h0, q0, h1, q1, h2, q2, h3, q3;
                hsplit(o[0], h0, q0); hsplit(o[1], h1, q1);
                hsplit(o[2], h2, q2); hsplit(o[3], h3, q3);
                *reinterpret_cast<uint32_t*>(oh + grow0) =
                    (uint32_t)__half_as_ushort(h0) |
                    ((uint32_t)__half_as_ushort(h1) << 16);
                *reinterpret_cast<uint32_t*>(ol + grow0) =
                    (uint32_t)__half_as_ushort(q0) |
                    ((uint32_t)__half_as_ushort(q1) << 16);
                *reinterpret_cast<uint32_t*>(oh + grow1) =
                    (uint32_t)__half_as_ushort(h2) |
                    ((uint32_t)__half_as_ushort(h3) << 16);
                *reinterpret_cast<uint32_t*>(ol + grow1) =
                    (uint32_t)__half_as_ushort(q2) |
                    ((uint32_t)__half_as_ushort(q3) << 16);
            }
        }
    }

    if (MODE == EP_LN_DUR) {
        float* red2 = reinterpret_cast<float*>(smem + RED2_OFF);
        const int nw = wid >> 2;
#pragma unroll
        for (int mf = 0; mf < 2; mf++)
#pragma unroll
            for (int hi = 0; hi < 2; hi++) {
                float d = dsum[mf][hi];
                d += __shfl_xor_sync(0xffffffffu, d, 1);
                d += __shfl_xor_sync(0xffffffffu, d, 2);
                if (tg == 0)
                    red2[(mBase + mf * 16 + g + hi * 8) * 4 + nw] = d;
            }
        __syncthreads();
        if ((wid >> 2) == 0 && tg == 0) {
            const float lb0 = __ldg(lb);
#pragma unroll
            for (int mf = 0; mf < 2; mf++)
#pragma unroll
                for (int hi = 0; hi < 2; hi++) {
                    const int r = mBase + mf * 16 + g + hi * 8;
                    dur[(size_t)(b * LL + l0 + r)] =
                        red2[r * 4 + 0] + red2[r * 4 + 1] +
                        red2[r * 4 + 2] + red2[r * 4 + 3] + lb0;
                }
        }
    }
}

// ---------------------------------------------------------------------------
// Split fp32 -> fp16 hi/lo (for initial x)
// ---------------------------------------------------------------------------
__global__ void split_kernel(const float* __restrict__ x,
                             __half* __restrict__ oh,
                             __half* __restrict__ ol, int n)
{
    int i = blockIdx.x * blockDim.x + threadIdx.x;
    if (i >= n) return;
    __half h, l;
    hsplit(x[i], h, l);
    oh[i] = h;
    ol[i] = l;
}

// ---------------------------------------------------------------------------
// Weight prep for all 4 layers (blockIdx.z = layer):
// w[co][ci][k] fp32 -> w[kappa][co] fp16 (kappa = k*384+ci)
// ---------------------------------------------------------------------------
__global__ void wprepT_kernel(const float* __restrict__ w0,
                              const float* __restrict__ w1,
                              const float* __restrict__ w2,
                              const float* __restrict__ w3,
                              __half* __restrict__ wb)
{
    __shared__ float t[32][33];
    const int layer = blockIdx.z;
    const float* w = (layer == 0) ? w0 : (layer == 1) ? w1 : (layer == 2) ? w2 : w3;
    __half* wt = wb + (size_t)layer * KTOT * DD;

    const int ka0 = blockIdx.x * 32;
    const int co0 = blockIdx.y * 32;
    const int tx = threadIdx.x, ty = threadIdx.y;
    const int k   = ka0 / DD;
    const int ci0 = ka0 - k * DD;

#pragma unroll
    for (int i = 0; i < 32; i += 8) {
        const int co = co0 + ty + i;
        const int ci = ci0 + tx;
        t[ty + i][tx] = w[(size_t)co * KTOT + ci * KK + k];
    }
    __syncthreads();
#pragma unroll
    for (int i = 0; i < 32; i += 8) {
        const int ka = ka0 + ty + i;
        const int co = co0 + tx;
        wt[(size_t)ka * DD + co] = __float2half_rn(t[tx][ty + i]);
    }
}

// ---------------------------------------------------------------------------
// Serial inclusive prefix scan: one thread per batch.
// ---------------------------------------------------------------------------
__global__ void serial_scan_kernel(const int* __restrict__ dur,
                                   int* __restrict__ cum,
                                   int* __restrict__ total)
{
    int b = threadIdx.x;
    if (b >= BB) return;
    int acc = 0;
    const int* dr = dur + b * LL;
    int* cr = cum + b * LL;
    for (int l = 0; l < LL; l++) {
        acc += dr[l];
        cr[l] = acc;
    }
    total[b] = acc;
}

// ---------------------------------------------------------------------------
// Length regulator scatter + tail zero (proven correct).
// ---------------------------------------------------------------------------
__global__ __launch_bounds__(128) void scatter_kernel(
    const float* __restrict__ x, const int* __restrict__ cum,
    float* __restrict__ out, int T)
{
    int l = blockIdx.x;
    int b = blockIdx.y;
    int lane = threadIdx.x;

    int end   = cum[b * LL + l];
    int start = (l == 0) ? 0 : cum[b * LL + l - 1];
    if (start == end) return;

    const float* xr = x + ((size_t)(b * LL + l)) * DD;
    float r0 = xr[lane];
    float r1 = xr[lane + 128];
    float r2 = xr[lane + 256];

    for (int t = start; t < end; t++) {
        float* o = out + ((size_t)b * T + t) * DD;
        o[lane]       = r0;
        o[lane + 128] = r1;
        o[lane + 256] = r2;
    }
}

__global__ __launch_bounds__(128) void zero_tail_kernel(
    const int* __restrict__ total, float* __restrict__ out, int T)
{
    int t = blockIdx.x;
    int b = blockIdx.y;
    if (t < total[b]) return;
    int lane = threadIdx.x;
    float* o = out + ((size_t)b * T + t) * DD;
    o[lane]       = 0.f;
    o[lane + 128] = 0.f;
    o[lane + 256] = 0.f;
}

// ---------------------------------------------------------------------------
extern "C" void kernel_launch(void* const* d_in, const int* in_sizes, int n_in,
                              void* d_out, int out_size)
{
    const float* x     = (const float*)d_in[0];
    const int*   dur   = (const int*)  d_in[1];
    const float* c1a_w = (const float*)d_in[2];
    const float* c1a_b = (const float*)d_in[3];
    const float* c1b_w = (const float*)d_in[4];
    const float* c1b_b = (const float*)d_in[5];
    const float* ln1_g = (const float*)d_in[6];
    const float* ln1_b = (const float*)d_in[7];
    const float* c2a_w = (const float*)d_in[8];
    const float* c2a_b = (const float*)d_in[9];
    const float* c2b_w = (const float*)d_in[10];
    const float* c2b_b = (const float*)d_in[11];
    const float* ln2_g = (const float*)d_in[12];
    const float* ln2_b = (const float*)d_in[13];
    const float* lin_w = (const float*)d_in[14];
    const float* lin_b = (const float*)d_in[15];
    float* out = (float*)d_out;

    long T = ((long)out_size - (long)BB * LL) / ((long)BB * DD);

    __half *ah, *al, *bh, *bl, *w;
    int *cum, *total;
    cudaGetSymbolAddress((void**)&ah,    g_ah);
    cudaGetSymbolAddress((void**)&al,    g_al);
    cudaGetSymbolAddress((void**)&bh,    g_bh);
    cudaGetSymbolAddress((void**)&bl,    g_bl);
    cudaGetSymbolAddress((void**)&w,     g_w);
    cudaGetSymbolAddress((void**)&cum,   g_cum);
    cudaGetSymbolAddress((void**)&total, g_total);

    cudaFuncSetAttribute(conv_mma_kernel<EP_SPLIT>,
                         cudaFuncAttributeMaxDynamicSharedMemorySize, SM_TOT);
    cudaFuncSetAttribute(conv_mma_kernel<EP_LN_SPLIT>,
                         cudaFuncAttributeMaxDynamicSharedMemorySize, SM_TOT);
    cudaFuncSetAttribute(conv_mma_kernel<EP_LN_DUR>,
                         cudaFuncAttributeMaxDynamicSharedMemorySize, SM_TOT);

    const int WN = KTOT * DD;
    const int n  = NROWS * DD;

    // Prep: operand splits (weights transposed to [kappa][co] fp16)
    split_kernel<<<(n + 255) / 256, 256>>>(x, ah, al, n);
    dim3 wtg(KTOT / 32, DD / 32, 4);
    dim3 wtb(32, 8);
    wprepT_kernel<<<wtg, wtb>>>(c1a_w, c1b_w, c2a_w, c2b_w, w);

    dim3 cgrid(LL / MT, BB);   // (4, 32) = 128 CTAs, single wave
    float* dur_out = out + (size_t)BB * T * DD;

    // Duration predictor (fp16 2-term HMMA convs; LN / lin head fused)
    conv_mma_kernel<EP_SPLIT><<<cgrid, CTT, SM_TOT>>>(
        ah, al, w,          c1a_b, nullptr, nullptr, nullptr, nullptr,
        bh, bl, nullptr);
    conv_mma_kernel<EP_LN_SPLIT><<<cgrid, CTT, SM_TOT>>>(
        bh, bl, w + WN,     c1b_b, ln1_g, ln1_b, nullptr, nullptr,
        ah, al, nullptr);
    conv_mma_kernel<EP_SPLIT><<<cgrid, CTT, SM_TOT>>>(
        ah, al, w + 2 * WN, c2a_b, nullptr, nullptr, nullptr, nullptr,
        bh, bl, nullptr);
    conv_mma_kernel<EP_LN_DUR><<<cgrid, CTT, SM_TOT>>>(
        bh, bl, w + 3 * WN, c2b_b, ln2_g, ln2_b, lin_w, lin_b,
        nullptr, nullptr, dur_out);

    // Length regulator
    serial_scan_kernel<<<1, BB>>>(dur, cum, total);
    zero_tail_kernel<<<dim3((unsigned)T, BB), 128>>>(total, out, (int)T);
    scatter_kernel<<<dim3(LL, BB), 128>>>(x, cum, out, (int)T);
}

// round 15
// speedup vs baseline: 1.0616x; 1.0607x over previous
#include <cuda_runtime.h>
#include <cuda_fp16.h>
#include <cstdint>

// Problem constants
#define BB 32
#define LL 512
#define DD 384
#define KK 3
#define KTOT (DD * KK)        // 1152 GEMM-K
#define NROWS (BB * LL)       // 16384 GEMM-M

// Conv MMA tiling
#define MT 128                // M rows per CTA (L-tile)
#define NT 384                // full c_out per CTA
#define KC 64                 // K chunk
#define NCHUNK (KTOT / KC)    // 18
#define CTT 512               // 16 warps: 4 m x 4 n

// smem per stage:
//   A tiles (row-major, 128 rows x 144B): 18432B each (h,l)
//   B tile  (k-major, 64 rows x 784B padded rows, 384 halves used): 50176B
#define A_TILE_B 18432
#define B_TILE_B 50176
#define SM_AH 0
#define SM_AL A_TILE_B
#define SM_B  (2 * A_TILE_B)
#define STAGE_B (2 * A_TILE_B + B_TILE_B)   // 87040
#define RED1_OFF (2 * STAGE_B)               // float2[128][4] = 4096B
#define RED2_OFF (RED1_OFF + 4096)           // float[128][4]  = 2048B
#define SM_TOT (RED2_OFF + 2048)             // 180224

// epilogue modes
#define EP_SPLIT 0
#define EP_LN_SPLIT 1
#define EP_LN_DUR 2

// ---------------- device scratch (allocation-free) -------------------------
__device__ __align__(16) __half g_ah[NROWS * DD];
__device__ __align__(16) __half g_al[NROWS * DD];
__device__ __align__(16) __half g_bh[NROWS * DD];
__device__ __align__(16) __half g_bl[NROWS * DD];
__device__ __align__(16) __half g_w[4][KTOT * DD];   // [kappa][co], fp16
__device__ int g_cum[BB * LL];
__device__ int g_total[BB];

// ---------------- helpers --------------------------------------------------
__device__ __forceinline__ void hsplit(float v, __half& h, __half& l) {
    h = __float2half_rn(v);
    l = __float2half_rn(v - __half2float(h));
}
__device__ __forceinline__ uint32_t smem_u32(const void* p) {
    uint32_t a;
    asm("{ .reg .u64 t; cvta.to.shared.u64 t, %1; cvt.u32.u64 %0, t; }"
        : "=r"(a) : "l"(p));
    return a;
}

#define CP16(dst, src, sz)                                                     \
    asm volatile("cp.async.cg.shared.global [%0], [%1], 16, %2;"               \
                 :: "r"(dst), "l"(src), "r"(sz) : "memory")
#define CP_COMMIT()  asm volatile("cp.async.commit_group;" ::: "memory")
#define CP_WAIT(n)   asm volatile("cp.async.wait_group %0;" :: "n"(n) : "memory")

#define MMA_F16(c, a0, a1, a2, a3, b0, b1)                                     \
    asm volatile(                                                              \
        "mma.sync.aligned.m16n8k16.row.col.f32.f16.f16.f32 "                   \
        "{%0,%1,%2,%3},{%4,%5,%6,%7},{%8,%9},{%0,%1,%2,%3};"                   \
        : "+f"((c)[0]), "+f"((c)[1]), "+f"((c)[2]), "+f"((c)[3])               \
        : "r"(a0), "r"(a1), "r"(a2), "r"(a3), "r"(b0), "r"(b1))

#define LDSM4(r0, r1, r2, r3, addr)                                            \
    asm volatile("ldmatrix.sync.aligned.m8n8.x4.shared.b16 {%0,%1,%2,%3}, [%4];" \
        : "=r"(r0), "=r"(r1), "=r"(r2), "=r"(r3) : "r"(addr))
#define LDSM4T(r0, r1, r2, r3, addr)                                           \
    asm volatile("ldmatrix.sync.aligned.m8n8.x4.trans.shared.b16 {%0,%1,%2,%3}, [%4];" \
        : "=r"(r0), "=r"(r1), "=r"(r2), "=r"(r3) : "r"(addr))

// ---------------------------------------------------------------------------
// Conv1D(K=3,SAME)+bias+ReLU as HMMA fp16 GEMM, 2-term A-split:
//   C = (Ah + Al) * B_fp16
// 2-stage cp.async pipeline, ldmatrix loads, 128x384 CTA tile (full row).
// Grid (4, 32) = 128 CTAs (single wave), 512 threads, warp tile 32x96.
// Inner loop processes the 12 n-fragments in two halves of 6 to cut the
// live-register set below the 128-reg RF clamp (kills mainloop spills).
// Epilogue modes: split only / fused LN + split / fused LN + linear head.
// ---------------------------------------------------------------------------
template<int MODE>
__global__ __launch_bounds__(CTT, 1) void conv_mma_kernel(
    const __half* __restrict__ ah, const __half* __restrict__ al,
    const __half* __restrict__ w,
    const float* __restrict__ bias,
    const float* __restrict__ gamma, const float* __restrict__ beta,
    const float* __restrict__ lw, const float* __restrict__ lb,
    __half* __restrict__ oh, __half* __restrict__ ol,
    float* __restrict__ dur)
{
    extern __shared__ char smem[];
    const uint32_t sb = smem_u32(smem);
    const int tid  = threadIdx.x;
    const int wid  = tid >> 5;
    const int lane = tid & 31;
    const int g    = lane >> 2;         // 0..7
    const int tg   = lane & 3;          // 0..3
    const int b    = blockIdx.y;
    const int l0   = blockIdx.x * MT;
    const int mBase = (wid & 3) * 32;   // 4 m-warps
    const int nBase = (wid >> 2) * 96;  // 4 n-warps

    // ldmatrix lane-address components
    const int aRowSel = lane & 15;
    const int aColSel = (lane >> 4) * 16;
    const int bKSel   = ((lane >> 3) & 1) * 8 + (lane & 7);
    const int bNSel   = (lane >> 4) * 8;

    float acc[2][12][4];
#pragma unroll
    for (int mf = 0; mf < 2; mf++)
#pragma unroll
        for (int nf = 0; nf < 12; nf++)
#pragma unroll
            for (int q = 0; q < 4; q++) acc[mf][nf][q] = 0.f;

    // ---- staging (cp.async) ----
    auto stage = [&](int c, int s) {
        const uint32_t base = sb + s * STAGE_B;
        const int kappa0 = c * KC;
        const int seg = kappa0 / DD;
        const int ci0 = kappa0 - seg * DD;
        // A tiles: 128 rows x 8 x 16B (h and l), shifted by seg-1, zfill halo
        for (int idx = tid; idx < MT * 8; idx += CTT) {
            const int r = idx >> 3, gg = idx & 7;
            const int l = l0 + r + seg - 1;
            const int ok = ((unsigned)l < LL) ? 16 : 0;
            const size_t go = ((size_t)(b * LL + ((unsigned)l < LL ? l : 0))) * DD
                              + ci0 + gg * 8;
            const uint32_t so = r * 144 + gg * 16;
            CP16(base + SM_AH + so, ah + go, ok);
            CP16(base + SM_AL + so, al + go, ok);
        }
        // B tile: 64 k-rows x 48 x 16B; gmem w is [kappa][co] fp16
        for (int idx = tid; idx < KC * 48; idx += CTT) {
            const int kr = idx / 48, gg = idx - kr * 48;
            const size_t go = (size_t)(kappa0 + kr) * DD + gg * 8;
            const uint32_t so = kr * 784 + gg * 16;
            CP16(base + SM_B + so, w + go, 16);
        }
        CP_COMMIT();
    };

    stage(0, 0);

    for (int c = 0; c < NCHUNK; c++) {
        const int s = c & 1;
        if (c + 1 < NCHUNK) {
            stage(c + 1, s ^ 1);
            CP_WAIT(1);
        } else {
            CP_WAIT(0);
        }
        __syncthreads();

        const uint32_t stA = sb + s * STAGE_B + SM_AH;
        const uint32_t stB = sb + s * STAGE_B + SM_B;

#pragma unroll
        for (int kk = 0; kk < 4; kk++) {            // K=16 steps in chunk
#pragma unroll
            for (int h = 0; h < 2; h++) {           // n-halves of 6 nf each
                // B fragments for this half: 3 LDSM4T -> 6 nf (12 regs live)
                uint32_t bf[6][2];
#pragma unroll
                for (int p = 0; p < 3; p++) {
                    const uint32_t bad = stB + (kk * 16 + bKSel) * 784
                                       + (nBase + h * 48 + p * 16 + bNSel) * 2;
                    LDSM4T(bf[p * 2][0], bf[p * 2][1],
                           bf[p * 2 + 1][0], bf[p * 2 + 1][1], bad);
                }
#pragma unroll
                for (int mf = 0; mf < 2; mf++) {
                    const uint32_t aad = stA + (mBase + mf * 16 + aRowSel) * 144
                                       + kk * 32 + aColSel;
                    uint32_t a0, a1, a2, a3, c0, c1, c2, c3;
                    LDSM4(a0, a1, a2, a3, aad);
                    LDSM4(c0, c1, c2, c3, aad + A_TILE_B);
                    // term-separated: dependent MMAs 6 issues apart
#pragma unroll
                    for (int nf = 0; nf < 6; nf++)
                        MMA_F16(acc[mf][h * 6 + nf], a0, a1, a2, a3,
                                bf[nf][0], bf[nf][1]);
#pragma unroll
                    for (int nf = 0; nf < 6; nf++)
                        MMA_F16(acc[mf][h * 6 + nf], c0, c1, c2, c3,
                                bf[nf][0], bf[nf][1]);
                }
            }
        }
        __syncthreads();   // compute done before buffer s is restaged
    }

    // ---- epilogue ----
    // bias + ReLU in place
#pragma unroll
    for (int nf = 0; nf < 12; nf++) {
        const int c0 = nBase + nf * 8 + tg * 2;
        const float bi0 = __ldg(bias + c0);
        const float bi1 = __ldg(bias + c0 + 1);
#pragma unroll
        for (int mf = 0; mf < 2; mf++) {
            acc[mf][nf][0] = fmaxf(acc[mf][nf][0] + bi0, 0.f);
            acc[mf][nf][1] = fmaxf(acc[mf][nf][1] + bi1, 0.f);
            acc[mf][nf][2] = fmaxf(acc[mf][nf][2] + bi0, 0.f);
            acc[mf][nf][3] = fmaxf(acc[mf][nf][3] + bi1, 0.f);
        }
    }

    float mu[2][2], rs[2][2];
    if (MODE >= EP_LN_SPLIT) {
        float2* red = reinterpret_cast<float2*>(smem + RED1_OFF);
        const int nw = wid >> 2;
#pragma unroll
        for (int mf = 0; mf < 2; mf++)
#pragma unroll
            for (int hi = 0; hi < 2; hi++) {
                float s = 0.f, s2 = 0.f;
#pragma unroll
                for (int nf = 0; nf < 12; nf++) {
                    float a = acc[mf][nf][hi * 2];
                    float bq = acc[mf][nf][hi * 2 + 1];
                    s  += a + bq;
                    s2 += a * a + bq * bq;
                }
                s  += __shfl_xor_sync(0xffffffffu, s, 1);
                s  += __shfl_xor_sync(0xffffffffu, s, 2);
                s2 += __shfl_xor_sync(0xffffffffu, s2, 1);
                s2 += __shfl_xor_sync(0xffffffffu, s2, 2);
                if (tg == 0)
                    red[(mBase + mf * 16 + g + hi * 8) * 4 + nw] =
                        make_float2(s, s2);
            }
        __syncthreads();
#pragma unroll
        for (int mf = 0; mf < 2; mf++)
#pragma unroll
            for (int hi = 0; hi < 2; hi++) {
                const int r = mBase + mf * 16 + g + hi * 8;
                float2 p0 = red[r * 4 + 0], p1 = red[r * 4 + 1];
                float2 p2 = red[r * 4 + 2], p3 = red[r * 4 + 3];
                float s  = p0.x + p1.x + p2.x + p3.x;
                float s2v = p0.y + p1.y + p2.y + p3.y;
                const float inv = 1.f / (float)DD;
                float m = s * inv;
                mu[mf][hi] = m;
                rs[mf][hi] = rsqrtf(s2v * inv - m * m + 1e-5f);
            }
    }

    float dsum[2][2] = {{0.f, 0.f}, {0.f, 0.f}};
#pragma unroll
    for (int nf = 0; nf < 12; nf++) {
        const int c0 = nBase + nf * 8 + tg * 2;
        float ga0 = 1.f, ga1 = 1.f, be0 = 0.f, be1 = 0.f, w0 = 0.f, w1 = 0.f;
        if (MODE >= EP_LN_SPLIT) {
            ga0 = __ldg(gamma + c0);  ga1 = __ldg(gamma + c0 + 1);
            be0 = __ldg(beta + c0);   be1 = __ldg(beta + c0 + 1);
        }
        if (MODE == EP_LN_DUR) {
            w0 = __ldg(lw + c0);      w1 = __ldg(lw + c0 + 1);
        }
#pragma unroll
        for (int mf = 0; mf < 2; mf++) {
            const int m0 = mBase + mf * 16 + g;
            float o[4];
#pragma unroll
            for (int hi = 0; hi < 2; hi++) {
                float v0 = acc[mf][nf][hi * 2];
                float v1 = acc[mf][nf][hi * 2 + 1];
                if (MODE >= EP_LN_SPLIT) {
                    v0 = (v0 - mu[mf][hi]) * rs[mf][hi] * ga0 + be0;
                    v1 = (v1 - mu[mf][hi]) * rs[mf][hi] * ga1 + be1;
                }
                o[hi * 2]     = v0;
                o[hi * 2 + 1] = v1;
                if (MODE == EP_LN_DUR)
                    dsum[mf][hi] += v0 * w0 + v1 * w1;
            }
            if (MODE != EP_LN_DUR) {
                const size_t grow0 = ((size_t)(b * LL + l0 + m0)) * DD + c0;
                const size_t grow1 = grow0 + 8 * DD;
                __half h0, q0, h1, q1, h2, q2, h3, q3;
                hsplit(o[0], h0, q0); hsplit(o[1], h1, q1);
                hsplit(o[2], h2, q2); hsplit(o[3], h3, q3);
                *reinterpret_cast<uint32_t*>(oh + grow0) =
                    (uint32_t)__half_as_ushort(h0) |
                    ((uint32_t)__half_as_ushort(h1) << 16);
                *reinterpret_cast<uint32_t*>(ol + grow0) =
                    (uint32_t)__half_as_ushort(q0) |
                    ((uint32_t)__half_as_ushort(q1) << 16);
                *reinterpret_cast<uint32_t*>(oh + grow1) =
                    (uint32_t)__half_as_ushort(h2) |
                    ((uint32_t)__half_as_ushort(h3) << 16);
                *reinterpret_cast<uint32_t*>(ol + grow1) =
                    (uint32_t)__half_as_ushort(q2) |
                    ((uint32_t)__half_as_ushort(q3) << 16);
            }
        }
    }

    if (MODE == EP_LN_DUR) {
        float* red2 = reinterpret_cast<float*>(smem + RED2_OFF);
        const int nw = wid >> 2;
#pragma unroll
        for (int mf = 0; mf < 2; mf++)
#pragma unroll
            for (int hi = 0; hi < 2; hi++) {
                float d = dsum[mf][hi];
                d += __shfl_xor_sync(0xffffffffu, d, 1);
                d += __shfl_xor_sync(0xffffffffu, d, 2);
                if (tg == 0)
                    red2[(mBase + mf * 16 + g + hi * 8) * 4 + nw] = d;
            }
        __syncthreads();
        if ((wid >> 2) == 0 && tg == 0) {
            const float lb0 = __ldg(lb);
#pragma unroll
            for (int mf = 0; mf < 2; mf++)
#pragma unroll
                for (int hi = 0; hi < 2; hi++) {
                    const int r = mBase + mf * 16 + g + hi * 8;
                    dur[(size_t)(b * LL + l0 + r)] =
                        red2[r * 4 + 0] + red2[r * 4 + 1] +
                        red2[r * 4 + 2] + red2[r * 4 + 3] + lb0;
                }
        }
    }
}

// ---------------------------------------------------------------------------
// Split fp32 -> fp16 hi/lo (for initial x)
// ---------------------------------------------------------------------------
__global__ void split_kernel(const float* __restrict__ x,
                             __half* __restrict__ oh,
                             __half* __restrict__ ol, int n)
{
    int i = blockIdx.x * blockDim.x + threadIdx.x;
    if (i >= n) return;
    __half h, l;
    hsplit(x[i], h, l);
    oh[i] = h;
    ol[i] = l;
}

// ---------------------------------------------------------------------------
// Weight prep for all 4 layers (blockIdx.z = layer):
// w[co][ci][k] fp32 -> w[kappa][co] fp16 (kappa = k*384+ci)
// ---------------------------------------------------------------------------
__global__ void wprepT_kernel(const float* __restrict__ w0,
                              const float* __restrict__ w1,
                              const float* __restrict__ w2,
                              const float* __restrict__ w3,
                              __half* __restrict__ wb)
{
    __shared__ float t[32][33];
    const int layer = blockIdx.z;
    const float* w = (layer == 0) ? w0 : (layer == 1) ? w1 : (layer == 2) ? w2 : w3;
    __half* wt = wb + (size_t)layer * KTOT * DD;

    const int ka0 = blockIdx.x * 32;
    const int co0 = blockIdx.y * 32;
    const int tx = threadIdx.x, ty = threadIdx.y;
    const int k   = ka0 / DD;
    const int ci0 = ka0 - k * DD;

#pragma unroll
    for (int i = 0; i < 32; i += 8) {
        const int co = co0 + ty + i;
        const int ci = ci0 + tx;
        t[ty + i][tx] = w[(size_t)co * KTOT + ci * KK + k];
    }
    __syncthreads();
#pragma unroll
    for (int i = 0; i < 32; i += 8) {
        const int ka = ka0 + ty + i;
        const int co = co0 + tx;
        wt[(size_t)ka * DD + co] = __float2half_rn(t[tx][ty + i]);
    }
}

// ---------------------------------------------------------------------------
// Serial inclusive prefix scan: one thread per batch.
// ---------------------------------------------------------------------------
__global__ void serial_scan_kernel(const int* __restrict__ dur,
                                   int* __restrict__ cum,
                                   int* __restrict__ total)
{
    int b = threadIdx.x;
    if (b >= BB) return;
    int acc = 0;
    const int* dr = dur + b * LL;
    int* cr = cum + b * LL;
    for (int l = 0; l < LL; l++) {
        acc += dr[l];
        cr[l] = acc;
    }
    total[b] = acc;
}

// ---------------------------------------------------------------------------
// Length regulator scatter + tail zero (proven correct).
// ---------------------------------------------------------------------------
__global__ __launch_bounds__(128) void scatter_kernel(
    const float* __restrict__ x, const int* __restrict__ cum,
    float* __restrict__ out, int T)
{
    int l = blockIdx.x;
    int b = blockIdx.y;
    int lane = threadIdx.x;

    int end   = cum[b * LL + l];
    int start = (l == 0) ? 0 : cum[b * LL + l - 1];
    if (start == end) return;

    const float* xr = x + ((size_t)(b * LL + l)) * DD;
    float r0 = xr[lane];
    float r1 = xr[lane + 128];
    float r2 = xr[lane + 256];

    for (int t = start; t < end; t++) {
        float* o = out + ((size_t)b * T + t) * DD;
        o[lane]       = r0;
        o[lane + 128] = r1;
        o[lane + 256] = r2;
    }
}

__global__ __launch_bounds__(128) void zero_tail_kernel(
    const int* __restrict__ total, float* __restrict__ out, int T)
{
    int t = blockIdx.x;
    int b = blockIdx.y;
    if (t < total[b]) return;
    int lane = threadIdx.x;
    float* o = out + ((size_t)b * T + t) * DD;
    o[lane]       = 0.f;
    o[lane + 128] = 0.f;
    o[lane + 256] = 0.f;
}

// ---------------------------------------------------------------------------
extern "C" void kernel_launch(void* const* d_in, const int* in_sizes, int n_in,
                              void* d_out, int out_size)
{
    const float* x     = (const float*)d_in[0];
    const int*   dur   = (const int*)  d_in[1];
    const float* c1a_w = (const float*)d_in[2];
    const float* c1a_b = (const float*)d_in[3];
    const float* c1b_w = (const float*)d_in[4];
    const float* c1b_b = (const float*)d_in[5];
    const float* ln1_g = (const float*)d_in[6];
    const float* ln1_b = (const float*)d_in[7];
    const float* c2a_w = (const float*)d_in[8];
    const float* c2a_b = (const float*)d_in[9];
    const float* c2b_w = (const float*)d_in[10];
    const float* c2b_b = (const float*)d_in[11];
    const float* ln2_g = (const float*)d_in[12];
    const float* ln2_b = (const float*)d_in[13];
    const float* lin_w = (const float*)d_in[14];
    const float* lin_b = (const float*)d_in[15];
    float* out = (float*)d_out;

    long T = ((long)out_size - (long)BB * LL) / ((long)BB * DD);

    __half *ah, *al, *bh, *bl, *w;
    int *cum, *total;
    cudaGetSymbolAddress((void**)&ah,    g_ah);
    cudaGetSymbolAddress((void**)&al,    g_al);
    cudaGetSymbolAddress((void**)&bh,    g_bh);
    cudaGetSymbolAddress((void**)&bl,    g_bl);
    cudaGetSymbolAddress((void**)&w,     g_w);
    cudaGetSymbolAddress((void**)&cum,   g_cum);
    cudaGetSymbolAddress((void**)&total, g_total);

    cudaFuncSetAttribute(conv_mma_kernel<EP_SPLIT>,
                         cudaFuncAttributeMaxDynamicSharedMemorySize, SM_TOT);
    cudaFuncSetAttribute(conv_mma_kernel<EP_LN_SPLIT>,
                         cudaFuncAttributeMaxDynamicSharedMemorySize, SM_TOT);
    cudaFuncSetAttribute(conv_mma_kernel<EP_LN_DUR>,
                         cudaFuncAttributeMaxDynamicSharedMemorySize, SM_TOT);

    const int WN = KTOT * DD;
    const int n  = NROWS * DD;

    // Prep: operand splits (weights transposed to [kappa][co] fp16)
    split_kernel<<<(n + 255) / 256, 256>>>(x, ah, al, n);
    dim3 wtg(KTOT / 32, DD / 32, 4);
    dim3 wtb(32, 8);
    wprepT_kernel<<<wtg, wtb>>>(c1a_w, c1b_w, c2a_w, c2b_w, w);

    dim3 cgrid(LL / MT, BB);   // (4, 32) = 128 CTAs, single wave
    float* dur_out = out + (size_t)BB * T * DD;

    // Duration predictor (fp16 2-term HMMA convs; LN / lin head fused)
    conv_mma_kernel<EP_SPLIT><<<cgrid, CTT, SM_TOT>>>(
        ah, al, w,          c1a_b, nullptr, nullptr, nullptr, nullptr,
        bh, bl, nullptr);
    conv_mma_kernel<EP_LN_SPLIT><<<cgrid, CTT, SM_TOT>>>(
        bh, bl, w + WN,     c1b_b, ln1_g, ln1_b, nullptr, nullptr,
        ah, al, nullptr);
    conv_mma_kernel<EP_SPLIT><<<cgrid, CTT, SM_TOT>>>(
        ah, al, w + 2 * WN, c2a_b, nullptr, nullptr, nullptr, nullptr,
        bh, bl, nullptr);
    conv_mma_kernel<EP_LN_DUR><<<cgrid, CTT, SM_TOT>>>(
        bh, bl, w + 3 * WN, c2b_b, ln2_g, ln2_b, lin_w, lin_b,
        nullptr, nullptr, dur_out);

    // Length regulator
    serial_scan_kernel<<<1, BB>>>(dur, cum, total);
    zero_tail_kernel<<<dim3((unsigned)T, BB), 128>>>(total, out, (int)T);
    scatter_kernel<<<dim3(LL, BB), 128>>>(x, cum, out, (int)T);
}

// round 17
// speedup vs baseline: 1.5802x; 1.4884x over previous
#include <cuda_runtime.h>
#include <cuda_fp16.h>
#include <cstdint>

// Problem constants
#define BB 32
#define LL 512
#define DD 384
#define KK 3
#define KTOT (DD * KK)        // 1152 GEMM-K
#define NROWS (BB * LL)       // 16384 GEMM-M

// Conv MMA tiling
#define MT 128                // M rows per CTA (L-tile)
#define NT 384                // full c_out per CTA
#define KC 64                 // K chunk
#define NCHUNK (KTOT / KC)    // 18
#define CTT 512               // 16 warps: 4 m x 4 n

// smem per stage:
//   A tile (row-major, 128 rows x 144B): 18432B
//   B tile (k-major, 64 rows x 784B padded rows, 384 halves used): 50176B
#define A_TILE_B 18432
#define B_TILE_B 50176
#define SM_A  0
#define SM_B  A_TILE_B
#define STAGE_B (A_TILE_B + B_TILE_B)        // 68608
#define RED1_OFF (3 * STAGE_B)               // float2[128][4] = 4096B
#define RED2_OFF (RED1_OFF + 4096)           // float[128][4]  = 2048B
#define SM_TOT (RED2_OFF + 2048)             // 211968 (3-stage)

// epilogue modes
#define EP_STORE 0
#define EP_LN_STORE 1
#define EP_LN_DUR 2

// ---------------- device scratch (allocation-free) -------------------------
__device__ __align__(16) __half g_a0[NROWS * DD];
__device__ __align__(16) __half g_a1[NROWS * DD];
__device__ __align__(16) __half g_w[4][KTOT * DD];   // [kappa][co], fp16
__device__ int g_cum[BB * LL];
__device__ int g_total[BB];

// ---------------- helpers --------------------------------------------------
__device__ __forceinline__ uint32_t smem_u32(const void* p) {
    uint32_t a;
    asm("{ .reg .u64 t; cvta.to.shared.u64 t, %1; cvt.u32.u64 %0, t; }"
        : "=r"(a) : "l"(p));
    return a;
}

#define CP16(dst, src, sz)                                                     \
    asm volatile("cp.async.cg.shared.global [%0], [%1], 16, %2;"               \
                 :: "r"(dst), "l"(src), "r"(sz) : "memory")
#define CP_COMMIT()  asm volatile("cp.async.commit_group;" ::: "memory")
#define CP_WAIT(n)   asm volatile("cp.async.wait_group %0;" :: "n"(n) : "memory")

#define MMA_F16(c, a0, a1, a2, a3, b0, b1)                                     \
    asm volatile(                                                              \
        "mma.sync.aligned.m16n8k16.row.col.f32.f16.f16.f32 "                   \
        "{%0,%1,%2,%3},{%4,%5,%6,%7},{%8,%9},{%0,%1,%2,%3};"                   \
        : "+f"((c)[0]), "+f"((c)[1]), "+f"((c)[2]), "+f"((c)[3])               \
        : "r"(a0), "r"(a1), "r"(a2), "r"(a3), "r"(b0), "r"(b1))

#define LDSM4(r0, r1, r2, r3, addr)                                            \
    asm volatile("ldmatrix.sync.aligned.m8n8.x4.shared.b16 {%0,%1,%2,%3}, [%4];" \
        : "=r"(r0), "=r"(r1), "=r"(r2), "=r"(r3) : "r"(addr))
#define LDSM4T(r0, r1, r2, r3, addr)                                           \
    asm volatile("ldmatrix.sync.aligned.m8n8.x4.trans.shared.b16 {%0,%1,%2,%3}, [%4];" \
        : "=r"(r0), "=r"(r1), "=r"(r2), "=r"(r3) : "r"(addr))

// ---------------------------------------------------------------------------
// Conv1D(K=3,SAME)+bias+ReLU as single-term fp16 HMMA GEMM: C = A_fp16 * B_fp16
// 3-stage cp.async pipeline, ONE __syncthreads per chunk, ldmatrix loads,
// 128x384 CTA tile (full row). Grid (4, 32) = 128 CTAs, 512 threads,
// warp tile 32x96 processed in two n-halves of 6 fragments (register diet).
// Epilogue: store fp16 / fused LN + store fp16 / fused LN + linear head.
// ---------------------------------------------------------------------------
template<int MODE>
__global__ __launch_bounds__(CTT, 1) void conv_mma_kernel(
    const __half* __restrict__ a, const __half* __restrict__ w,
    const float* __restrict__ bias,
    const float* __restrict__ gamma, const float* __restrict__ beta,
    const float* __restrict__ lw, const float* __restrict__ lb,
    __half* __restrict__ o, float* __restrict__ dur)
{
    extern __shared__ char smem[];
    const uint32_t sb = smem_u32(smem);
    const int tid  = threadIdx.x;
    const int wid  = tid >> 5;
    const int lane = tid & 31;
    const int g    = lane >> 2;         // 0..7
    const int tg   = lane & 3;          // 0..3
    const int b    = blockIdx.y;
    const int l0   = blockIdx.x * MT;
    const int mBase = (wid & 3) * 32;   // 4 m-warps
    const int nBase = (wid >> 2) * 96;  // 4 n-warps

    // ldmatrix lane-address components
    const int aRowSel = lane & 15;
    const int aColSel = (lane >> 4) * 16;
    const int bKSel   = ((lane >> 3) & 1) * 8 + (lane & 7);
    const int bNSel   = (lane >> 4) * 8;

    float acc[2][12][4];
#pragma unroll
    for (int mf = 0; mf < 2; mf++)
#pragma unroll
        for (int nf = 0; nf < 12; nf++)
#pragma unroll
            for (int q = 0; q < 4; q++) acc[mf][nf][q] = 0.f;

    // ---- staging (cp.async), one commit group per chunk ----
    auto stage = [&](int c, int s) {
        const uint32_t base = sb + s * STAGE_B;
        const int kappa0 = c * KC;
        const int seg = kappa0 / DD;
        const int ci0 = kappa0 - seg * DD;
        // A tile: 128 rows x 8 x 16B, shifted by seg-1, zfill halo
        for (int idx = tid; idx < MT * 8; idx += CTT) {
            const int r = idx >> 3, gg = idx & 7;
            const int l = l0 + r + seg - 1;
            const int ok = ((unsigned)l < LL) ? 16 : 0;
            const size_t go = ((size_t)(b * LL + ((unsigned)l < LL ? l : 0))) * DD
                              + ci0 + gg * 8;
            CP16(base + SM_A + r * 144 + gg * 16, a + go, ok);
        }
        // B tile: 64 k-rows x 48 x 16B; gmem w is [kappa][co] fp16
        for (int idx = tid; idx < KC * 48; idx += CTT) {
            const int kr = idx / 48, gg = idx - kr * 48;
            const size_t go = (size_t)(kappa0 + kr) * DD + gg * 8;
            CP16(base + SM_B + kr * 784 + gg * 16, w + go, 16);
        }
        CP_COMMIT();
    };

    stage(0, 0);
    stage(1, 1);

    for (int c = 0; c < NCHUNK; c++) {
        const int s = c % 3;
        // wait for chunk c's group (the next chunk's group may stay in flight)
        if (c + 1 < NCHUNK) CP_WAIT(1); else CP_WAIT(0);
        __syncthreads();   // data visible to all; all warps done with chunk c-1
        if (c + 2 < NCHUNK) stage(c + 2, (c + 2) % 3);  // overwrites chunk c-1 buf

        const uint32_t stA = sb + s * STAGE_B + SM_A;
        const uint32_t stB = sb + s * STAGE_B + SM_B;

#pragma unroll
        for (int kk = 0; kk < 4; kk++) {            // K=16 steps in chunk
#pragma unroll
            for (int h = 0; h < 2; h++) {           // n-halves of 6 nf each
                uint32_t bf[6][2];
#pragma unroll
                for (int p = 0; p < 3; p++) {
                    const uint32_t bad = stB + (kk * 16 + bKSel) * 784
                                       + (nBase + h * 48 + p * 16 + bNSel) * 2;
                    LDSM4T(bf[p * 2][0], bf[p * 2][1],
                           bf[p * 2 + 1][0], bf[p * 2 + 1][1], bad);
                }
#pragma unroll
                for (int mf = 0; mf < 2; mf++) {
                    const uint32_t aad = stA + (mBase + mf * 16 + aRowSel) * 144
                                       + kk * 32 + aColSel;
                    uint32_t a0, a1, a2, a3;
                    LDSM4(a0, a1, a2, a3, aad);
#pragma unroll
                    for (int nf = 0; nf < 6; nf++)
                        MMA_F16(acc[mf][h * 6 + nf], a0, a1, a2, a3,
                                bf[nf][0], bf[nf][1]);
                }
            }
        }
    }

    // ---- epilogue ----
    // bias + ReLU in place
#pragma unroll
    for (int nf = 0; nf < 12; nf++) {
        const int c0 = nBase + nf * 8 + tg * 2;
        const float bi0 = __ldg(bias + c0);
        const float bi1 = __ldg(bias + c0 + 1);
#pragma unroll
        for (int mf = 0; mf < 2; mf++) {
            acc[mf][nf][0] = fmaxf(acc[mf][nf][0] + bi0, 0.f);
            acc[mf][nf][1] = fmaxf(acc[mf][nf][1] + bi1, 0.f);
            acc[mf][nf][2] = fmaxf(acc[mf][nf][2] + bi0, 0.f);
            acc[mf][nf][3] = fmaxf(acc[mf][nf][3] + bi1, 0.f);
        }
    }

    float mu[2][2], rs[2][2];
    if (MODE >= EP_LN_STORE) {
        float2* red = reinterpret_cast<float2*>(smem + RED1_OFF);
        const int nw = wid >> 2;
#pragma unroll
        for (int mf = 0; mf < 2; mf++)
#pragma unroll
            for (int hi = 0; hi < 2; hi++) {
                float s = 0.f, s2 = 0.f;
#pragma unroll
                for (int nf = 0; nf < 12; nf++) {
                    float aa = acc[mf][nf][hi * 2];
                    float bb = acc[mf][nf][hi * 2 + 1];
                    s  += aa + bb;
                    s2 += aa * aa + bb * bb;
                }
                s  += __shfl_xor_sync(0xffffffffu, s, 1);
                s  += __shfl_xor_sync(0xffffffffu, s, 2);
                s2 += __shfl_xor_sync(0xffffffffu, s2, 1);
                s2 += __shfl_xor_sync(0xffffffffu, s2, 2);
                if (tg == 0)
                    red[(mBase + mf * 16 + g + hi * 8) * 4 + nw] =
                        make_float2(s, s2);
            }
        __syncthreads();
#pragma unroll
        for (int mf = 0; mf < 2; mf++)
#pragma unroll
            for (int hi = 0; hi < 2; hi++) {
                const int r = mBase + mf * 16 + g + hi * 8;
                float2 p0 = red[r * 4 + 0], p1 = red[r * 4 + 1];
                float2 p2 = red[r * 4 + 2], p3 = red[r * 4 + 3];
                float s  = p0.x + p1.x + p2.x + p3.x;
                float s2v = p0.y + p1.y + p2.y + p3.y;
                const float inv = 1.f / (float)DD;
                float m = s * inv;
                mu[mf][hi] = m;
                rs[mf][hi] = rsqrtf(s2v * inv - m * m + 1e-5f);
            }
    }

    float dsum[2][2] = {{0.f, 0.f}, {0.f, 0.f}};
#pragma unroll
    for (int nf = 0; nf < 12; nf++) {
        const int c0 = nBase + nf * 8 + tg * 2;
        float ga0 = 1.f, ga1 = 1.f, be0 = 0.f, be1 = 0.f, w0 = 0.f, w1 = 0.f;
        if (MODE >= EP_LN_STORE) {
            ga0 = __ldg(gamma + c0);  ga1 = __ldg(gamma + c0 + 1);
            be0 = __ldg(beta + c0);   be1 = __ldg(beta + c0 + 1);
        }
        if (MODE == EP_LN_DUR) {
            w0 = __ldg(lw + c0);      w1 = __ldg(lw + c0 + 1);
        }
#pragma unroll
        for (int mf = 0; mf < 2; mf++) {
            const int m0 = mBase + mf * 16 + g;
            float ov[4];
#pragma unroll
            for (int hi = 0; hi < 2; hi++) {
                float v0 = acc[mf][nf][hi * 2];
                float v1 = acc[mf][nf][hi * 2 + 1];
                if (MODE >= EP_LN_STORE) {
                    v0 = (v0 - mu[mf][hi]) * rs[mf][hi] * ga0 + be0;
                    v1 = (v1 - mu[mf][hi]) * rs[mf][hi] * ga1 + be1;
                }
                ov[hi * 2]     = v0;
                ov[hi * 2 + 1] = v1;
                if (MODE == EP_LN_DUR)
                    dsum[mf][hi] += v0 * w0 + v1 * w1;
            }
            if (MODE != EP_LN_DUR) {
                const size_t grow0 = ((size_t)(b * LL + l0 + m0)) * DD + c0;
                const size_t grow1 = grow0 + 8 * DD;
                __half h0 = __float2half_rn(ov[0]);
                __half h1 = __float2half_rn(ov[1]);
                __half h2 = __float2half_rn(ov[2]);
                __half h3 = __float2half_rn(ov[3]);
                *reinterpret_cast<uint32_t*>(o + grow0) =
                    (uint32_t)__half_as_ushort(h0) |
                    ((uint32_t)__half_as_ushort(h1) << 16);
                *reinterpret_cast<uint32_t*>(o + grow1) =
                    (uint32_t)__half_as_ushort(h2) |
                    ((uint32_t)__half_as_ushort(h3) << 16);
            }
        }
    }

    if (MODE == EP_LN_DUR) {
        float* red2 = reinterpret_cast<float*>(smem + RED2_OFF);
        const int nw = wid >> 2;
#pragma unroll
        for (int mf = 0; mf < 2; mf++)
#pragma unroll
            for (int hi = 0; hi < 2; hi++) {
                float d = dsum[mf][hi];
                d += __shfl_xor_sync(0xffffffffu, d, 1);
                d += __shfl_xor_sync(0xffffffffu, d, 2);
                if (tg == 0)
                    red2[(mBase + mf * 16 + g + hi * 8) * 4 + nw] = d;
            }
        __syncthreads();
        if ((wid >> 2) == 0 && tg == 0) {
            const float lb0 = __ldg(lb);
#pragma unroll
            for (int mf = 0; mf < 2; mf++)
#pragma unroll
                for (int hi = 0; hi < 2; hi++) {
                    const int r = mBase + mf * 16 + g + hi * 8;
                    dur[(size_t)(b * LL + l0 + r)] =
                        red2[r * 4 + 0] + red2[r * 4 + 1] +
                        red2[r * 4 + 2] + red2[r * 4 + 3] + lb0;
                }
        }
    }
}

// ---------------------------------------------------------------------------
// Convert fp32 -> fp16 (for initial x)
// ---------------------------------------------------------------------------
__global__ void cvt_kernel(const float* __restrict__ x,
                           __half* __restrict__ o, int n)
{
    int i = blockIdx.x * blockDim.x + threadIdx.x;
    if (i >= n) return;
    o[i] = __float2half_rn(x[i]);
}

// ---------------------------------------------------------------------------
// Weight prep for all 4 layers (blockIdx.z = layer):
// w[co][ci][k] fp32 -> w[kappa][co] fp16 (kappa = k*384+ci)
// ---------------------------------------------------------------------------
__global__ void wprepT_kernel(const float* __restrict__ w0,
                              const float* __restrict__ w1,
                              const float* __restrict__ w2,
                              const float* __restrict__ w3,
                              __half* __restrict__ wb)
{
    __shared__ float t[32][33];
    const int layer = blockIdx.z;
    const float* w = (layer == 0) ? w0 : (layer == 1) ? w1 : (layer == 2) ? w2 : w3;
    __half* wt = wb + (size_t)layer * KTOT * DD;

    const int ka0 = blockIdx.x * 32;
    const int co0 = blockIdx.y * 32;
    const int tx = threadIdx.x, ty = threadIdx.y;
    const int k   = ka0 / DD;
    const int ci0 = ka0 - k * DD;

#pragma unroll
    for (int i = 0; i < 32; i += 8) {
        const int co = co0 + ty + i;
        const int ci = ci0 + tx;
        t[ty + i][tx] = w[(size_t)co * KTOT + ci * KK + k];
    }
    __syncthreads();
#pragma unroll
    for (int i = 0; i < 32; i += 8) {
        const int ka = ka0 + ty + i;
        const int co = co0 + tx;
        wt[(size_t)ka * DD + co] = __float2half_rn(t[tx][ty + i]);
    }
}

// ---------------------------------------------------------------------------
// Serial inclusive prefix scan: one thread per batch.
// ---------------------------------------------------------------------------
__global__ void serial_scan_kernel(const int* __restrict__ dur,
                                   int* __restrict__ cum,
                                   int* __restrict__ total)
{
    int b = threadIdx.x;
    if (b >= BB) return;
    int acc = 0;
    const int* dr = dur + b * LL;
    int* cr = cum + b * LL;
    for (int l = 0; l < LL; l++) {
        acc += dr[l];
        cr[l] = acc;
    }
    total[b] = acc;
}

// ---------------------------------------------------------------------------
// Length regulator scatter + tail zero (proven correct).
// ---------------------------------------------------------------------------
__global__ __launch_bounds__(128) void scatter_kernel(
    const float* __restrict__ x, const int* __restrict__ cum,
    float* __restrict__ out, int T)
{
    int l = blockIdx.x;
    int b = blockIdx.y;
    int lane = threadIdx.x;

    int end   = cum[b * LL + l];
    int start = (l == 0) ? 0 : cum[b * LL + l - 1];
    if (start == end) return;

    const float* xr = x + ((size_t)(b * LL + l)) * DD;
    float r0 = xr[lane];
    float r1 = xr[lane + 128];
    float r2 = xr[lane + 256];

    for (int t = start; t < end; t++) {
        float* o = out + ((size_t)b * T + t) * DD;
        o[lane]       = r0;
        o[lane + 128] = r1;
        o[lane + 256] = r2;
    }
}

__global__ __launch_bounds__(128) void zero_tail_kernel(
    const int* __restrict__ total, float* __restrict__ out, int T)
{
    int t = blockIdx.x;
    int b = blockIdx.y;
    if (t < total[b]) return;
    int lane = threadIdx.x;
    float* o = out + ((size_t)b * T + t) * DD;
    o[lane]       = 0.f;
    o[lane + 128] = 0.f;
    o[lane + 256] = 0.f;
}

// ---------------------------------------------------------------------------
extern "C" void kernel_launch(void* const* d_in, const int* in_sizes, int n_in,
                              void* d_out, int out_size)
{
    const float* x     = (const float*)d_in[0];
    const int*   dur   = (const int*)  d_in[1];
    const float* c1a_w = (const float*)d_in[2];
    const float* c1a_b = (const float*)d_in[3];
    const float* c1b_w = (const float*)d_in[4];
    const float* c1b_b = (const float*)d_in[5];
    const float* ln1_g = (const float*)d_in[6];
    const float* ln1_b = (const float*)d_in[7];
    const float* c2a_w = (const float*)d_in[8];
    const float* c2a_b = (const float*)d_in[9];
    const float* c2b_w = (const float*)d_in[10];
    const float* c2b_b = (const float*)d_in[11];
    const float* ln2_g = (const float*)d_in[12];
    const float* ln2_b = (const float*)d_in[13];
    const float* lin_w = (const float*)d_in[14];
    const float* lin_b = (const float*)d_in[15];
    float* out = (float*)d_out;

    long T = ((long)out_size - (long)BB * LL) / ((long)BB * DD);

    __half *a0, *a1, *w;
    int *cum, *total;
    cudaGetSymbolAddress((void**)&a0,    g_a0);
    cudaGetSymbolAddress((void**)&a1,    g_a1);
    cudaGetSymbolAddress((void**)&w,     g_w);
    cudaGetSymbolAddress((void**)&cum,   g_cum);
    cudaGetSymbolAddress((void**)&total, g_total);

    cudaFuncSetAttribute(conv_mma_kernel<EP_STORE>,
                         cudaFuncAttributeMaxDynamicSharedMemorySize, SM_TOT);
    cudaFuncSetAttribute(conv_mma_kernel<EP_LN_STORE>,
                         cudaFuncAttributeMaxDynamicSharedMemorySize, SM_TOT);
    cudaFuncSetAttribute(conv_mma_kernel<EP_LN_DUR>,
                         cudaFuncAttributeMaxDynamicSharedMemorySize, SM_TOT);

    const int WN = KTOT * DD;
    const int n  = NROWS * DD;

    // Prep: x -> fp16, weights transposed to [kappa][co] fp16
    cvt_kernel<<<(n + 255) / 256, 256>>>(x, a0, n);
    dim3 wtg(KTOT / 32, DD / 32, 4);
    dim3 wtb(32, 8);
    wprepT_kernel<<<wtg, wtb>>>(c1a_w, c1b_w, c2a_w, c2b_w, w);

    dim3 cgrid(LL / MT, BB);   // (4, 32) = 128 CTAs, single wave
    float* dur_out = out + (size_t)BB * T * DD;

    // Duration predictor (single-term fp16 HMMA convs; LN / lin head fused)
    conv_mma_kernel<EP_STORE><<<cgrid, CTT, SM_TOT>>>(
        a0, w,          c1a_b, nullptr, nullptr, nullptr, nullptr, a1, nullptr);
    conv_mma_kernel<EP_LN_STORE><<<cgrid, CTT, SM_TOT>>>(
        a1, w + WN,     c1b_b, ln1_g, ln1_b, nullptr, nullptr, a0, nullptr);
    conv_mma_kernel<EP_STORE><<<cgrid, CTT, SM_TOT>>>(
        a0, w + 2 * WN, c2a_b, nullptr, nullptr, nullptr, nullptr, a1, nullptr);
    conv_mma_kernel<EP_LN_DUR><<<cgrid, CTT, SM_TOT>>>(
        a1, w + 3 * WN, c2b_b, ln2_g, ln2_b, lin_w, lin_b, nullptr, dur_out);

    // Length regulator
    serial_scan_kernel<<<1, BB>>>(dur, cum, total);
    zero_tail_kernel<<<dim3((unsigned)T, BB), 128>>>(total, out, (int)T);
    scatter_kernel<<<dim3(LL, BB), 128>>>(x, cum, out, (int)T);
}